// round 12
// baseline (speedup 1.0000x reference)
#include <cuda_runtime.h>
#include <cuda_fp16.h>

#define D 64
#define MAXN 100000
#define MAXE 1600000
#define MAXV 1024

typedef unsigned long long ull;

// ---------------- f32x2 packed helpers (Blackwell) ----------------
__device__ __forceinline__ ull d_pack(float lo, float hi) {
    ull r; asm("mov.b64 %0, {%1, %2};" : "=l"(r) : "f"(lo), "f"(hi)); return r;
}
__device__ __forceinline__ float2 d_unpack(ull v) {
    float2 r; asm("mov.b64 {%0, %1}, %2;" : "=f"(r.x), "=f"(r.y) : "l"(v)); return r;
}
__device__ __forceinline__ ull d_dup(float v) {
    ull r; asm("mov.b64 %0, {%1, %1};" : "=l"(r) : "f"(v)); return r;
}
__device__ __forceinline__ ull d_fma2(ull a, ull b, ull c) {
    ull d; asm("fma.rn.f32x2 %0, %1, %2, %3;" : "=l"(d) : "l"(a), "l"(b), "l"(c)); return d;
}

// ---------------- static scratch ----------------
__device__ int     g_rowptr[MAXN + 1];
__device__ int     g_cursor[MAXN];
__device__ uint4   g_edge[MAXE];           // {src, ea01(half2), ea23(half2), pad}, dst-sorted
__device__ float   g_X[MAXN * D];          // node features (fp32)
__device__ __half2 g_Ha[MAXN * 32];        // H buffer A (fp16; index i = dims (2i, 2i+1))
__device__ __half2 g_Hb[MAXN * 32];        // H buffer B
__device__ float   g_embH[MAXV * D];       // emb @ Wx1^T + b1
__device__ int     g_aggflag[128];         // per-chunk aggregate | READY bit
__device__ int     g_ticks[2];             // dynamic work counters for round kernels

#define SCAN_READY (1 << 30)

// ---------------- kA: zero cursor/flags/ticks + zero out + embH ----------------
__global__ void k_init(const float* __restrict__ emb, const float* __restrict__ W1,
                       const float* __restrict__ b1, float* __restrict__ out, int N, int V) {
    int b = blockIdx.x, t = threadIdx.x;
    int base = b * 1024 + t * 4;
#pragma unroll
    for (int j = 0; j < 4; j++)
        if (base + j < N) g_cursor[base + j] = 0;
    if (b == 0) {
        if (t < 64) out[t] = 0.0f;
        if (t >= 64 && t < 192) g_aggflag[t - 64] = 0;
        if (t == 192) { g_ticks[0] = 0; g_ticks[1] = 0; }
    }
    if (b < V && t < 64) {
        const float* er = emb + b * D;
        const float* wr = W1 + t * 68;
        float acc = b1[t];
#pragma unroll 16
        for (int j = 0; j < D; j++) acc = fmaf(er[j], wr[j], acc);
        g_embH[b * D + t] = acc;
    }
}

// ---------------- kB: histogram of dst + (parallel) gather X0/Ha ----------------
__global__ void k_hist_gather(const int* __restrict__ dst, const int* __restrict__ ids,
                              const float* __restrict__ emb, int E, int N, int SB) {
    int b = blockIdx.x;
    if (b < SB) {
        int e = b * 256 + threadIdx.x;
        if (e < E) atomicAdd(&g_cursor[dst[e]], 1);
    } else {
        int i = (b - SB) * 256 + threadIdx.x;
        if (i < N * 16) {
            int n = i >> 4, c = i & 15;
            int id = ids[n];
            reinterpret_cast<float4*>(g_X)[i] = reinterpret_cast<const float4*>(emb)[id * 16 + c];
            float4 h4 = reinterpret_cast<const float4*>(g_embH)[id * 16 + c];
            g_Ha[n * 32 + 2 * c]     = __floats2half2_rn(h4.x, h4.y);
            g_Ha[n * 32 + 2 * c + 1] = __floats2half2_rn(h4.z, h4.w);
        }
    }
}

// ---------------- kC: fused scan (local scan + parallel lookback) ----------------
__global__ void k_scan(int N, int E, int nb) {
    __shared__ int s[256];
    int b = blockIdx.x, t = threadIdx.x;
    int base = b * 1024 + t * 4;
    int v0 = (base + 0 < N) ? g_cursor[base + 0] : 0;
    int v1 = (base + 1 < N) ? g_cursor[base + 1] : 0;
    int v2 = (base + 2 < N) ? g_cursor[base + 2] : 0;
    int v3 = (base + 3 < N) ? g_cursor[base + 3] : 0;
    int tsum = v0 + v1 + v2 + v3;
    s[t] = tsum;
    __syncthreads();
    for (int off = 1; off < 256; off <<= 1) {
        int x = (t >= off) ? s[t - off] : 0;
        __syncthreads();
        s[t] += x;
        __syncthreads();
    }
    int excl = s[t] - tsum;
    int total = s[255];
    __syncthreads();
    if (t == 0) atomicExch(&g_aggflag[b], total | SCAN_READY);
    int contrib = 0;
    if (t < b) {
        int v;
        do { v = atomicAdd(&g_aggflag[t], 0); } while (!(v & SCAN_READY));
        contrib = v & (SCAN_READY - 1);
    }
    s[t] = contrib;
    __syncthreads();
    for (int off = 128; off > 0; off >>= 1) {
        if (t < off) s[t] += s[t + off];
        __syncthreads();
    }
    int boff = s[0];
    int r0 = excl + boff;
#pragma unroll
    for (int j = 0; j < 4; j++) {
        int i = base + j;
        if (i < N) {
            g_rowptr[i] = r0;
            g_cursor[i] = r0;
        }
        r0 += (j == 0) ? v0 : (j == 1) ? v1 : v2;
    }
    if (b == 0 && t == 0) g_rowptr[N] = E;
}

// ---------------- kD: scatter packed edge records (R10-verified format) ----------------
__global__ void k_scatter(const int* __restrict__ src, const int* __restrict__ dst,
                          const float* __restrict__ ea, int E) {
    int e = blockIdx.x * 256 + threadIdx.x;
    if (e < E) {
        int p = atomicAdd(&g_cursor[dst[e]], 1);
        float4 v = *reinterpret_cast<const float4*>(ea + 4 * (size_t)e);
        __half2 e01 = __floats2half2_rn(v.x, v.y);
        __half2 e23 = __floats2half2_rn(v.z, v.w);
        uint4 rec;
        rec.x = (unsigned)src[e];
        rec.y = *reinterpret_cast<const unsigned*>(&e01);
        rec.z = *reinterpret_cast<const unsigned*>(&e23);
        rec.w = 0u;
        g_edge[p] = rec;
    }
}

// ======= shared building blocks for the fused round kernels =======

__device__ __forceinline__ void fill_wint(float* Wf, const float* __restrict__ W, int stride, int t) {
    for (int idx = t; idx < 4096; idx += 256) {
        int jj = idx >> 7, r = idx & 127;
        int l = r >> 2, q = (r >> 1) & 1, h = r & 1;
        Wf[idx] = W[(2 * l + h) * stride + (2 * jj + q)];
    }
}

__device__ __forceinline__ void mv64_8(ull* a2, const ull* Wi, const float* yd8, int lane) {
#pragma unroll 4
    for (int jj = 0; jj < 32; jj++) {
        longlong2 wv = *reinterpret_cast<const longlong2*>(Wi + jj * 64 + 2 * lane);
#pragma unroll
        for (int n = 0; n < 8; n++) {
            longlong2 xv = *reinterpret_cast<const longlong2*>(yd8 + n * 128 + 4 * jj);
            a2[n] = d_fma2((ull)xv.x, (ull)wv.x, a2[n]);
            a2[n] = d_fma2((ull)xv.y, (ull)wv.y, a2[n]);
        }
    }
}

// one edge given {ea01, ea23} words and hv (half4 in uint2)
__device__ __forceinline__ void edge_accum_w(unsigned ea01, unsigned ea23, uint2 hvu,
                                             const ull* wpa, const ull* wpb, bool act,
                                             float& a0, float& a1, float& a2v, float& a3) {
    float2 e01 = __half22float2(*reinterpret_cast<const __half2*>(&ea01));
    float2 e23 = __half22float2(*reinterpret_cast<const __half2*>(&ea23));
    float2 h0 = __half22float2(*reinterpret_cast<const __half2*>(&hvu.x));
    float2 h1 = __half22float2(*reinterpret_cast<const __half2*>(&hvu.y));
    ull m0 = d_pack(h0.x, h0.y);
    ull m1 = d_pack(h1.x, h1.y);
    ull e0 = d_dup(e01.x), e1 = d_dup(e01.y), e2 = d_dup(e23.x), e3 = d_dup(e23.y);
    m0 = d_fma2(e0, wpa[0], m0); m0 = d_fma2(e1, wpa[1], m0);
    m0 = d_fma2(e2, wpa[2], m0); m0 = d_fma2(e3, wpa[3], m0);
    m1 = d_fma2(e0, wpb[0], m1); m1 = d_fma2(e1, wpb[1], m1);
    m1 = d_fma2(e2, wpb[2], m1); m1 = d_fma2(e3, wpb[3], m1);
    if (act) {
        float2 f0 = d_unpack(m0), f1 = d_unpack(m1);
        a0 += fmaxf(f0.x, 0.0f); a1 += fmaxf(f0.y, 0.0f);
        a2v += fmaxf(f1.x, 0.0f); a3 += fmaxf(f1.y, 0.0f);
    }
}

// half-warp agg. Main loop: 16-edge blocks — lane hl loads record k0+i+hl (coalesced
// 256B per half-warp), then each edge's {src, ea} is shuffle-broadcast within the half.
// Tail: R10's depth-4 + scalar broadcast path.
__device__ __forceinline__ void agg_pair(float* ydrow_base, const __half2* __restrict__ H,
                                         const ull* wpa, const ull* wpb,
                                         int n0, int p, int half, int hl, int N) {
    int nn = n0 + 2 * p + half;
    bool valid = nn < N;
    int nc = valid ? nn : 0;
    int k0 = g_rowptr[nc], k1 = g_rowptr[nc + 1];
    int len = valid ? (k1 - k0) : 0;
    int maxlen = __reduce_max_sync(0xffffffffu, len);
    float a0 = 0.f, a1 = 0.f, a2v = 0.f, a3 = 0.f;
    if (valid) {
        float4 x0 = *reinterpret_cast<const float4*>(g_X + nn * D + 4 * hl);
        a0 = x0.x; a1 = x0.y; a2v = x0.z; a3 = x0.w;
    }
    int hbase = half << 4;
    int i = 0;
    for (; i + 16 <= maxlen; i += 16) {
        int idx = i + hl;
        uint4 rec = g_edge[(idx < len) ? (k0 + idx) : 0];
#pragma unroll
        for (int jb = 0; jb < 4; jb++) {
            unsigned sj[4], w1[4], w2[4];
#pragma unroll
            for (int j = 0; j < 4; j++) {
                int sl = hbase + jb * 4 + j;
                sj[j] = __shfl_sync(0xffffffffu, rec.x, sl);
                w1[j] = __shfl_sync(0xffffffffu, rec.y, sl);
                w2[j] = __shfl_sync(0xffffffffu, rec.z, sl);
            }
            uint2 hv[4];
#pragma unroll
            for (int j = 0; j < 4; j++)
                hv[j] = *reinterpret_cast<const uint2*>(H + (int)sj[j] * 32 + 2 * hl);
#pragma unroll
            for (int j = 0; j < 4; j++)
                edge_accum_w(w1[j], w2[j], hv[j], wpa, wpb, i + jb * 4 + j < len,
                             a0, a1, a2v, a3);
        }
    }
    for (; i + 4 <= maxlen; i += 4) {
        bool act0 = (i + 0 < len), act1 = (i + 1 < len);
        bool act2 = (i + 2 < len), act3 = (i + 3 < len);
        uint4 r0 = g_edge[act0 ? (k0 + i + 0) : 0];
        uint4 r1 = g_edge[act1 ? (k0 + i + 1) : 0];
        uint4 r2 = g_edge[act2 ? (k0 + i + 2) : 0];
        uint4 r3 = g_edge[act3 ? (k0 + i + 3) : 0];
        uint2 h0 = *reinterpret_cast<const uint2*>(H + (int)r0.x * 32 + 2 * hl);
        uint2 h1 = *reinterpret_cast<const uint2*>(H + (int)r1.x * 32 + 2 * hl);
        uint2 h2 = *reinterpret_cast<const uint2*>(H + (int)r2.x * 32 + 2 * hl);
        uint2 h3 = *reinterpret_cast<const uint2*>(H + (int)r3.x * 32 + 2 * hl);
        edge_accum_w(r0.y, r0.z, h0, wpa, wpb, act0, a0, a1, a2v, a3);
        edge_accum_w(r1.y, r1.z, h1, wpa, wpb, act1, a0, a1, a2v, a3);
        edge_accum_w(r2.y, r2.z, h2, wpa, wpb, act2, a0, a1, a2v, a3);
        edge_accum_w(r3.y, r3.z, h3, wpa, wpb, act3, a0, a1, a2v, a3);
    }
    for (; i < maxlen; i++) {
        bool act = (i < len);
        uint4 r = g_edge[act ? (k0 + i) : 0];
        uint2 hv = *reinterpret_cast<const uint2*>(H + (int)r.x * 32 + 2 * hl);
        edge_accum_w(r.y, r.z, hv, wpa, wpb, act, a0, a1, a2v, a3);
    }
    float* row = ydrow_base + (2 * p + half) * 128 + 8 * hl;
    *reinterpret_cast<float4*>(row)     = make_float4(a0, a0, a1, a1);
    *reinterpret_cast<float4*>(row + 4) = make_float4(a2v, a2v, a3, a3);
}

// dynamic ticket: warp-uniform next group index
__device__ __forceinline__ int next_group(int* tick, int lane) {
    int g;
    if (lane == 0) g = atomicAdd(tick, 1);
    return __shfl_sync(0xffffffffu, g, 0);
}

// ---------------- fused round 1 (8 nodes/warp; dynamic smem: Wus|Wns|yd) ----------------
__global__ void __launch_bounds__(256, 3) k_round1(const float* __restrict__ W1,
                                                   const float* __restrict__ Wu, const float* __restrict__ bu,
                                                   const float* __restrict__ Wn, const float* __restrict__ bn,
                                                   int N) {
    extern __shared__ __align__(16) ull smem_dyn[];
    ull* Wus = smem_dyn;                 // 16KB
    ull* Wns = smem_dyn + 2048;          // 16KB
    float* ydall = reinterpret_cast<float*>(smem_dyn + 4096);  // 32KB
    int t = threadIdx.x;
    fill_wint(reinterpret_cast<float*>(Wus), Wu, 64, t);
    fill_wint(reinterpret_cast<float*>(Wns), Wn, 68, t);
    __syncthreads();

    int lane = t & 31, w = t >> 5;
    int half = lane >> 4, hl = lane & 15;
    float* yd = ydall + w * 1024;

    float4 q0 = *reinterpret_cast<const float4*>(W1 + (4 * hl) * 68 + 64);
    float4 q1 = *reinterpret_cast<const float4*>(W1 + (4 * hl + 1) * 68 + 64);
    float4 q2 = *reinterpret_cast<const float4*>(W1 + (4 * hl + 2) * 68 + 64);
    float4 q3 = *reinterpret_cast<const float4*>(W1 + (4 * hl + 3) * 68 + 64);
    ull wpa[4] = {d_pack(q0.x, q1.x), d_pack(q0.y, q1.y), d_pack(q0.z, q1.z), d_pack(q0.w, q1.w)};
    ull wpb[4] = {d_pack(q2.x, q3.x), d_pack(q2.y, q3.y), d_pack(q2.z, q3.z), d_pack(q2.w, q3.w)};

    float bu0 = bu[2 * lane], bu1 = bu[2 * lane + 1];
    float bn0 = bn[2 * lane], bn1 = bn[2 * lane + 1];

    int ng = (N + 7) >> 3;
    for (;;) {
        int g = next_group(&g_ticks[0], lane);
        if (g >= ng) break;
        int n0 = g * 8;
        agg_pair(yd, g_Ha, wpa, wpb, n0, 0, half, hl, N);
        agg_pair(yd, g_Ha, wpa, wpb, n0, 1, half, hl, N);
        agg_pair(yd, g_Ha, wpa, wpb, n0, 2, half, hl, N);
        agg_pair(yd, g_Ha, wpa, wpb, n0, 3, half, hl, N);
        __syncwarp();
        ull a2[8] = {0ull, 0ull, 0ull, 0ull, 0ull, 0ull, 0ull, 0ull};
        mv64_8(a2, Wus, yd, lane);
        __syncwarp();
#pragma unroll
        for (int n = 0; n < 8; n++) {
            float2 a = d_unpack(a2[n]);
            a.x = fmaxf(a.x + bu0, 0.0f);
            a.y = fmaxf(a.y + bu1, 0.0f);
            int nn = n0 + n;
            if (nn < N) *reinterpret_cast<float2*>(g_X + nn * D + 2 * lane) = a;
            *reinterpret_cast<ull*>(&yd[n * 128 + 4 * lane])     = d_dup(a.x);
            *reinterpret_cast<ull*>(&yd[n * 128 + 4 * lane + 2]) = d_dup(a.y);
        }
        __syncwarp();
        ull h2[8] = {0ull, 0ull, 0ull, 0ull, 0ull, 0ull, 0ull, 0ull};
        mv64_8(h2, Wns, yd, lane);
        __syncwarp();
#pragma unroll
        for (int n = 0; n < 8; n++) {
            float2 h = d_unpack(h2[n]);
            int nn = n0 + n;
            if (nn < N) g_Hb[nn * 32 + lane] = __floats2half2_rn(h.x + bn0, h.y + bn1);
        }
    }
}

// ---------------- fused round 2: agg + final matvec + mean ----------------
__global__ void __launch_bounds__(256, 3) k_round2(const float* __restrict__ W2,
                                                   const float* __restrict__ Wu, const float* __restrict__ bu,
                                                   float* __restrict__ out, int N) {
    extern __shared__ __align__(16) ull smem_dyn[];
    ull* Wus = smem_dyn;                                        // 16KB
    float* ydall = reinterpret_cast<float*>(smem_dyn + 2048);   // 32KB
    float* sacc = ydall + 8192;                                 // 64 floats
    int t = threadIdx.x;
    fill_wint(reinterpret_cast<float*>(Wus), Wu, 64, t);
    if (t < 64) sacc[t] = 0.0f;
    __syncthreads();

    int lane = t & 31, w = t >> 5;
    int half = lane >> 4, hl = lane & 15;
    float* yd = ydall + w * 1024;

    float4 q0 = *reinterpret_cast<const float4*>(W2 + (4 * hl) * 68 + 64);
    float4 q1 = *reinterpret_cast<const float4*>(W2 + (4 * hl + 1) * 68 + 64);
    float4 q2 = *reinterpret_cast<const float4*>(W2 + (4 * hl + 2) * 68 + 64);
    float4 q3 = *reinterpret_cast<const float4*>(W2 + (4 * hl + 3) * 68 + 64);
    ull wpa[4] = {d_pack(q0.x, q1.x), d_pack(q0.y, q1.y), d_pack(q0.z, q1.z), d_pack(q0.w, q1.w)};
    ull wpb[4] = {d_pack(q2.x, q3.x), d_pack(q2.y, q3.y), d_pack(q2.z, q3.z), d_pack(q2.w, q3.w)};

    float bu0 = bu[2 * lane], bu1 = bu[2 * lane + 1];
    float2 tot = make_float2(0.0f, 0.0f);

    int ng = (N + 7) >> 3;
    for (;;) {
        int g = next_group(&g_ticks[1], lane);
        if (g >= ng) break;
        int n0 = g * 8;
        agg_pair(yd, g_Hb, wpa, wpb, n0, 0, half, hl, N);
        agg_pair(yd, g_Hb, wpa, wpb, n0, 1, half, hl, N);
        agg_pair(yd, g_Hb, wpa, wpb, n0, 2, half, hl, N);
        agg_pair(yd, g_Hb, wpa, wpb, n0, 3, half, hl, N);
        __syncwarp();
        ull a2[8] = {0ull, 0ull, 0ull, 0ull, 0ull, 0ull, 0ull, 0ull};
        mv64_8(a2, Wus, yd, lane);
        __syncwarp();
#pragma unroll
        for (int n = 0; n < 8; n++) {
            int nn = n0 + n;
            if (nn < N) {
                float2 a = d_unpack(a2[n]);
                tot.x += fmaxf(a.x + bu0, 0.0f);
                tot.y += fmaxf(a.y + bu1, 0.0f);
            }
        }
    }
    atomicAdd(&sacc[2 * lane], tot.x);
    atomicAdd(&sacc[2 * lane + 1], tot.y);
    __syncthreads();
    if (t < 64) atomicAdd(&out[t], sacc[t] * (1.0f / (float)N));
}

// ---------------- launch ----------------
extern "C" void kernel_launch(void* const* d_in, const int* in_sizes, int n_in,
                              void* d_out, int out_size) {
    const int*   x_ids = (const int*)d_in[0];
    const int*   eidx  = (const int*)d_in[1];
    const float* eattr = (const float*)d_in[2];
    const float* emb   = (const float*)d_in[3];
    const float* W1  = (const float*)d_in[4];
    const float* b1  = (const float*)d_in[5];
    const float* Wu1 = (const float*)d_in[6];
    const float* bu1 = (const float*)d_in[7];
    const float* W2  = (const float*)d_in[8];
    const float* b2  = (const float*)d_in[9];
    const float* Wu2 = (const float*)d_in[10];
    const float* bu2 = (const float*)d_in[11];
    float* out = (float*)d_out;

    int N = in_sizes[0];
    int E = in_sizes[1] / 2;
    int V = in_sizes[3] / D;
    const int* src = eidx;
    const int* dst = eidx + E;

    int nb = (N + 1023) / 1024;
    int gA = nb > V ? nb : V;
    int SB = (E + 255) / 256;
    int GB = (N * 16 + 255) / 256;

    const int R1_SMEM = 65536;   // Wus 16K + Wns 16K + yd 32K
    const int R2_SMEM = 49408;   // Wus 16K + yd 32K + sacc 256B
    cudaFuncSetAttribute(k_round1, cudaFuncAttributeMaxDynamicSharedMemorySize, R1_SMEM);
    cudaFuncSetAttribute(k_round2, cudaFuncAttributeMaxDynamicSharedMemorySize, R2_SMEM);

    k_init<<<gA, 256>>>(emb, W1, b1, out, N, V);
    k_hist_gather<<<SB + GB, 256>>>(dst, x_ids, emb, E, N, SB);
    k_scan<<<nb, 256>>>(N, E, nb);
    k_scatter<<<SB, 256>>>(src, dst, eattr, E);

    const int RG = 444;   // 3 blocks/SM x 148 SMs, single wave
    k_round1<<<RG, 256, R1_SMEM>>>(W1, Wu1, bu1, W2, b2, N);
    k_round2<<<RG, 256, R2_SMEM>>>(W2, Wu2, bu2, out, N);
}

// round 13
// speedup vs baseline: 1.0826x; 1.0826x over previous
#include <cuda_runtime.h>
#include <cuda_fp16.h>

#define D 64
#define MAXN 100000
#define MAXE 1600000
#define MAXV 1024

typedef unsigned long long ull;

// ---------------- f32x2 packed helpers (Blackwell) ----------------
__device__ __forceinline__ ull d_pack(float lo, float hi) {
    ull r; asm("mov.b64 %0, {%1, %2};" : "=l"(r) : "f"(lo), "f"(hi)); return r;
}
__device__ __forceinline__ float2 d_unpack(ull v) {
    float2 r; asm("mov.b64 {%0, %1}, %2;" : "=f"(r.x), "=f"(r.y) : "l"(v)); return r;
}
__device__ __forceinline__ ull d_dup(float v) {
    ull r; asm("mov.b64 %0, {%1, %1};" : "=l"(r) : "f"(v)); return r;
}
__device__ __forceinline__ ull d_fma2(ull a, ull b, ull c) {
    ull d; asm("fma.rn.f32x2 %0, %1, %2, %3;" : "=l"(d) : "l"(a), "l"(b), "l"(c)); return d;
}

// ---------------- static scratch ----------------
__device__ int     g_rowptr[MAXN + 1];
__device__ int     g_cursor[MAXN];
__device__ uint4   g_edge[MAXE];           // {src, ea01(half2), ea23(half2), pad}, dst-sorted
__device__ float   g_X[MAXN * D];          // node features (fp32)
__device__ __half2 g_Ha[MAXN * 32];        // H buffer A (fp16; index i = dims (2i, 2i+1))
__device__ __half2 g_Hb[MAXN * 32];        // H buffer B
__device__ float   g_embH[MAXV * D];       // emb @ Wx1^T + b1
__device__ int     g_aggflag[128];         // per-chunk aggregate | READY bit
__device__ int     g_ticks[2];             // dynamic work counters for round kernels

#define SCAN_READY (1 << 30)

// ---------------- kA: zero cursor/flags/ticks + zero out + embH ----------------
__global__ void k_init(const float* __restrict__ emb, const float* __restrict__ W1,
                       const float* __restrict__ b1, float* __restrict__ out, int N, int V) {
    int b = blockIdx.x, t = threadIdx.x;
    int base = b * 1024 + t * 4;
#pragma unroll
    for (int j = 0; j < 4; j++)
        if (base + j < N) g_cursor[base + j] = 0;
    if (b == 0) {
        if (t < 64) out[t] = 0.0f;
        if (t >= 64 && t < 192) g_aggflag[t - 64] = 0;
        if (t == 192) { g_ticks[0] = 0; g_ticks[1] = 0; }
    }
    if (b < V && t < 64) {
        const float* er = emb + b * D;
        const float* wr = W1 + t * 68;
        float acc = b1[t];
#pragma unroll 16
        for (int j = 0; j < D; j++) acc = fmaf(er[j], wr[j], acc);
        g_embH[b * D + t] = acc;
    }
}

// ---------------- kB: histogram of dst + (parallel) gather X0/Ha ----------------
__global__ void k_hist_gather(const int* __restrict__ dst, const int* __restrict__ ids,
                              const float* __restrict__ emb, int E, int N, int SB) {
    int b = blockIdx.x;
    if (b < SB) {
        int e = b * 256 + threadIdx.x;
        if (e < E) atomicAdd(&g_cursor[dst[e]], 1);
    } else {
        int i = (b - SB) * 256 + threadIdx.x;
        if (i < N * 16) {
            int n = i >> 4, c = i & 15;
            int id = ids[n];
            reinterpret_cast<float4*>(g_X)[i] = reinterpret_cast<const float4*>(emb)[id * 16 + c];
            float4 h4 = reinterpret_cast<const float4*>(g_embH)[id * 16 + c];
            g_Ha[n * 32 + 2 * c]     = __floats2half2_rn(h4.x, h4.y);
            g_Ha[n * 32 + 2 * c + 1] = __floats2half2_rn(h4.z, h4.w);
        }
    }
}

// ---------------- kC: fused scan (local scan + parallel lookback) ----------------
__global__ void k_scan(int N, int E, int nb) {
    __shared__ int s[256];
    int b = blockIdx.x, t = threadIdx.x;
    int base = b * 1024 + t * 4;
    int v0 = (base + 0 < N) ? g_cursor[base + 0] : 0;
    int v1 = (base + 1 < N) ? g_cursor[base + 1] : 0;
    int v2 = (base + 2 < N) ? g_cursor[base + 2] : 0;
    int v3 = (base + 3 < N) ? g_cursor[base + 3] : 0;
    int tsum = v0 + v1 + v2 + v3;
    s[t] = tsum;
    __syncthreads();
    for (int off = 1; off < 256; off <<= 1) {
        int x = (t >= off) ? s[t - off] : 0;
        __syncthreads();
        s[t] += x;
        __syncthreads();
    }
    int excl = s[t] - tsum;
    int total = s[255];
    __syncthreads();
    if (t == 0) atomicExch(&g_aggflag[b], total | SCAN_READY);
    int contrib = 0;
    if (t < b) {
        int v;
        do { v = atomicAdd(&g_aggflag[t], 0); } while (!(v & SCAN_READY));
        contrib = v & (SCAN_READY - 1);
    }
    s[t] = contrib;
    __syncthreads();
    for (int off = 128; off > 0; off >>= 1) {
        if (t < off) s[t] += s[t + off];
        __syncthreads();
    }
    int boff = s[0];
    int r0 = excl + boff;
#pragma unroll
    for (int j = 0; j < 4; j++) {
        int i = base + j;
        if (i < N) {
            g_rowptr[i] = r0;
            g_cursor[i] = r0;
        }
        r0 += (j == 0) ? v0 : (j == 1) ? v1 : v2;
    }
    if (b == 0 && t == 0) g_rowptr[N] = E;
}

// ---------------- kD: scatter packed edge records (R10-verified format) ----------------
__global__ void k_scatter(const int* __restrict__ src, const int* __restrict__ dst,
                          const float* __restrict__ ea, int E) {
    int e = blockIdx.x * 256 + threadIdx.x;
    if (e < E) {
        int p = atomicAdd(&g_cursor[dst[e]], 1);
        float4 v = *reinterpret_cast<const float4*>(ea + 4 * (size_t)e);
        __half2 e01 = __floats2half2_rn(v.x, v.y);
        __half2 e23 = __floats2half2_rn(v.z, v.w);
        uint4 rec;
        rec.x = (unsigned)src[e];
        rec.y = *reinterpret_cast<const unsigned*>(&e01);
        rec.z = *reinterpret_cast<const unsigned*>(&e23);
        rec.w = 0u;
        g_edge[p] = rec;
    }
}

// ======= shared building blocks for the fused round kernels =======

__device__ __forceinline__ void fill_wint(float* Wf, const float* __restrict__ W, int stride, int t) {
    for (int idx = t; idx < 4096; idx += 256) {
        int jj = idx >> 7, r = idx & 127;
        int l = r >> 2, q = (r >> 1) & 1, h = r & 1;
        Wf[idx] = W[(2 * l + h) * stride + (2 * jj + q)];
    }
}

__device__ __forceinline__ void mv64_8(ull* a2, const ull* Wi, const float* yd8, int lane) {
#pragma unroll 4
    for (int jj = 0; jj < 32; jj++) {
        longlong2 wv = *reinterpret_cast<const longlong2*>(Wi + jj * 64 + 2 * lane);
#pragma unroll
        for (int n = 0; n < 8; n++) {
            longlong2 xv = *reinterpret_cast<const longlong2*>(yd8 + n * 128 + 4 * jj);
            a2[n] = d_fma2((ull)xv.x, (ull)wv.x, a2[n]);
            a2[n] = d_fma2((ull)xv.y, (ull)wv.y, a2[n]);
        }
    }
}

// process one packed edge record for this lane's 4 dims
__device__ __forceinline__ void edge_accum(uint4 rec, uint2 hv,
                                           const ull* wpa, const ull* wpb, bool act,
                                           float& a0, float& a1, float& a2v, float& a3) {
    float2 e01 = __half22float2(*reinterpret_cast<const __half2*>(&rec.y));
    float2 e23 = __half22float2(*reinterpret_cast<const __half2*>(&rec.z));
    float2 h0 = __half22float2(*reinterpret_cast<const __half2*>(&hv.x));
    float2 h1 = __half22float2(*reinterpret_cast<const __half2*>(&hv.y));
    ull m0 = d_pack(h0.x, h0.y);
    ull m1 = d_pack(h1.x, h1.y);
    ull e0 = d_dup(e01.x), e1 = d_dup(e01.y), e2 = d_dup(e23.x), e3 = d_dup(e23.y);
    m0 = d_fma2(e0, wpa[0], m0); m0 = d_fma2(e1, wpa[1], m0);
    m0 = d_fma2(e2, wpa[2], m0); m0 = d_fma2(e3, wpa[3], m0);
    m1 = d_fma2(e0, wpb[0], m1); m1 = d_fma2(e1, wpb[1], m1);
    m1 = d_fma2(e2, wpb[2], m1); m1 = d_fma2(e3, wpb[3], m1);
    if (act) {
        float2 f0 = d_unpack(m0), f1 = d_unpack(m1);
        a0 += fmaxf(f0.x, 0.0f); a1 += fmaxf(f0.y, 0.0f);
        a2v += fmaxf(f1.x, 0.0f); a3 += fmaxf(f1.y, 0.0f);
    }
}

// half-warp agg for node pair; lane owns dims 4hl..4hl+3; 4-deep pipeline (R10-verified).
__device__ __forceinline__ void agg_pair(float* ydrow_base, const __half2* __restrict__ H,
                                         const ull* wpa, const ull* wpb,
                                         int n0, int p, int half, int hl, int N) {
    int nn = n0 + 2 * p + half;
    bool valid = nn < N;
    int nc = valid ? nn : 0;
    int k0 = g_rowptr[nc], k1 = g_rowptr[nc + 1];
    int len = valid ? (k1 - k0) : 0;
    int maxlen = __reduce_max_sync(0xffffffffu, len);
    float a0 = 0.f, a1 = 0.f, a2v = 0.f, a3 = 0.f;
    if (valid) {
        float4 x0 = *reinterpret_cast<const float4*>(g_X + nn * D + 4 * hl);
        a0 = x0.x; a1 = x0.y; a2v = x0.z; a3 = x0.w;
    }
    const uint4* eb = g_edge + k0;
    int i = 0;
    for (; i + 4 <= maxlen; i += 4) {
        bool act0 = (i + 0 < len), act1 = (i + 1 < len);
        bool act2 = (i + 2 < len), act3 = (i + 3 < len);
        uint4 r0 = eb[act0 ? (i + 0) : -k0];
        uint4 r1 = eb[act1 ? (i + 1) : -k0];
        uint4 r2 = eb[act2 ? (i + 2) : -k0];
        uint4 r3 = eb[act3 ? (i + 3) : -k0];
        uint2 h0 = *reinterpret_cast<const uint2*>(H + (int)r0.x * 32 + 2 * hl);
        uint2 h1 = *reinterpret_cast<const uint2*>(H + (int)r1.x * 32 + 2 * hl);
        uint2 h2 = *reinterpret_cast<const uint2*>(H + (int)r2.x * 32 + 2 * hl);
        uint2 h3 = *reinterpret_cast<const uint2*>(H + (int)r3.x * 32 + 2 * hl);
        edge_accum(r0, h0, wpa, wpb, act0, a0, a1, a2v, a3);
        edge_accum(r1, h1, wpa, wpb, act1, a0, a1, a2v, a3);
        edge_accum(r2, h2, wpa, wpb, act2, a0, a1, a2v, a3);
        edge_accum(r3, h3, wpa, wpb, act3, a0, a1, a2v, a3);
    }
    if (i < maxlen) {
        bool act0 = (i + 0 < len), act1 = (i + 1 < len), act2 = (i + 2 < len);
        uint4 r0 = eb[act0 ? (i + 0) : -k0];
        uint4 r1 = (i + 1 < maxlen) ? eb[act1 ? (i + 1) : -k0] : make_uint4(0, 0, 0, 0);
        uint4 r2 = (i + 2 < maxlen) ? eb[act2 ? (i + 2) : -k0] : make_uint4(0, 0, 0, 0);
        uint2 h0 = *reinterpret_cast<const uint2*>(H + (int)r0.x * 32 + 2 * hl);
        uint2 h1 = *reinterpret_cast<const uint2*>(H + (int)r1.x * 32 + 2 * hl);
        uint2 h2 = *reinterpret_cast<const uint2*>(H + (int)r2.x * 32 + 2 * hl);
        edge_accum(r0, h0, wpa, wpb, act0, a0, a1, a2v, a3);
        if (i + 1 < maxlen) edge_accum(r1, h1, wpa, wpb, act1, a0, a1, a2v, a3);
        if (i + 2 < maxlen) edge_accum(r2, h2, wpa, wpb, act2, a0, a1, a2v, a3);
    }
    float* row = ydrow_base + (2 * p + half) * 128 + 8 * hl;
    *reinterpret_cast<float4*>(row)     = make_float4(a0, a0, a1, a1);
    *reinterpret_cast<float4*>(row + 4) = make_float4(a2v, a2v, a3, a3);
}

// dynamic ticket: warp-uniform next pair of group indices (1 ATOMG per 2 groups)
__device__ __forceinline__ int next_group2(int* tick, int lane) {
    int g;
    if (lane == 0) g = atomicAdd(tick, 2);
    return __shfl_sync(0xffffffffu, g, 0);
}

// ---------------- fused round 1 (8 nodes/warp; dynamic smem: Wus|Wns|yd) ----------------
__global__ void __launch_bounds__(256, 3) k_round1(const float* __restrict__ W1,
                                                   const float* __restrict__ Wu, const float* __restrict__ bu,
                                                   const float* __restrict__ Wn, const float* __restrict__ bn,
                                                   int N) {
    extern __shared__ __align__(16) ull smem_dyn[];
    ull* Wus = smem_dyn;                 // 16KB
    ull* Wns = smem_dyn + 2048;          // 16KB
    float* ydall = reinterpret_cast<float*>(smem_dyn + 4096);  // 32KB
    int t = threadIdx.x;
    fill_wint(reinterpret_cast<float*>(Wus), Wu, 64, t);
    fill_wint(reinterpret_cast<float*>(Wns), Wn, 68, t);
    __syncthreads();

    int lane = t & 31, w = t >> 5;
    int half = lane >> 4, hl = lane & 15;
    float* yd = ydall + w * 1024;

    float4 q0 = *reinterpret_cast<const float4*>(W1 + (4 * hl) * 68 + 64);
    float4 q1 = *reinterpret_cast<const float4*>(W1 + (4 * hl + 1) * 68 + 64);
    float4 q2 = *reinterpret_cast<const float4*>(W1 + (4 * hl + 2) * 68 + 64);
    float4 q3 = *reinterpret_cast<const float4*>(W1 + (4 * hl + 3) * 68 + 64);
    ull wpa[4] = {d_pack(q0.x, q1.x), d_pack(q0.y, q1.y), d_pack(q0.z, q1.z), d_pack(q0.w, q1.w)};
    ull wpb[4] = {d_pack(q2.x, q3.x), d_pack(q2.y, q3.y), d_pack(q2.z, q3.z), d_pack(q2.w, q3.w)};

    float bu0 = bu[2 * lane], bu1 = bu[2 * lane + 1];
    float bn0 = bn[2 * lane], bn1 = bn[2 * lane + 1];

    int ng = (N + 7) >> 3;
    for (;;) {
        int gpair = next_group2(&g_ticks[0], lane);
        if (gpair >= ng) break;
#pragma unroll 1
        for (int g = gpair; g < gpair + 2 && g < ng; g++) {
            int n0 = g * 8;
            agg_pair(yd, g_Ha, wpa, wpb, n0, 0, half, hl, N);
            agg_pair(yd, g_Ha, wpa, wpb, n0, 1, half, hl, N);
            agg_pair(yd, g_Ha, wpa, wpb, n0, 2, half, hl, N);
            agg_pair(yd, g_Ha, wpa, wpb, n0, 3, half, hl, N);
            __syncwarp();
            ull a2[8] = {0ull, 0ull, 0ull, 0ull, 0ull, 0ull, 0ull, 0ull};
            mv64_8(a2, Wus, yd, lane);
            __syncwarp();
#pragma unroll
            for (int n = 0; n < 8; n++) {
                float2 a = d_unpack(a2[n]);
                a.x = fmaxf(a.x + bu0, 0.0f);
                a.y = fmaxf(a.y + bu1, 0.0f);
                int nn = n0 + n;
                if (nn < N) *reinterpret_cast<float2*>(g_X + nn * D + 2 * lane) = a;
                *reinterpret_cast<ull*>(&yd[n * 128 + 4 * lane])     = d_dup(a.x);
                *reinterpret_cast<ull*>(&yd[n * 128 + 4 * lane + 2]) = d_dup(a.y);
            }
            __syncwarp();
            ull h2[8] = {0ull, 0ull, 0ull, 0ull, 0ull, 0ull, 0ull, 0ull};
            mv64_8(h2, Wns, yd, lane);
            __syncwarp();
#pragma unroll
            for (int n = 0; n < 8; n++) {
                float2 h = d_unpack(h2[n]);
                int nn = n0 + n;
                if (nn < N) g_Hb[nn * 32 + lane] = __floats2half2_rn(h.x + bn0, h.y + bn1);
            }
        }
    }
}

// ---------------- fused round 2: agg + final matvec + mean ----------------
__global__ void __launch_bounds__(256, 3) k_round2(const float* __restrict__ W2,
                                                   const float* __restrict__ Wu, const float* __restrict__ bu,
                                                   float* __restrict__ out, int N) {
    extern __shared__ __align__(16) ull smem_dyn[];
    ull* Wus = smem_dyn;                                        // 16KB
    float* ydall = reinterpret_cast<float*>(smem_dyn + 2048);   // 32KB
    float* sacc = ydall + 8192;                                 // 64 floats
    int t = threadIdx.x;
    fill_wint(reinterpret_cast<float*>(Wus), Wu, 64, t);
    if (t < 64) sacc[t] = 0.0f;
    __syncthreads();

    int lane = t & 31, w = t >> 5;
    int half = lane >> 4, hl = lane & 15;
    float* yd = ydall + w * 1024;

    float4 q0 = *reinterpret_cast<const float4*>(W2 + (4 * hl) * 68 + 64);
    float4 q1 = *reinterpret_cast<const float4*>(W2 + (4 * hl + 1) * 68 + 64);
    float4 q2 = *reinterpret_cast<const float4*>(W2 + (4 * hl + 2) * 68 + 64);
    float4 q3 = *reinterpret_cast<const float4*>(W2 + (4 * hl + 3) * 68 + 64);
    ull wpa[4] = {d_pack(q0.x, q1.x), d_pack(q0.y, q1.y), d_pack(q0.z, q1.z), d_pack(q0.w, q1.w)};
    ull wpb[4] = {d_pack(q2.x, q3.x), d_pack(q2.y, q3.y), d_pack(q2.z, q3.z), d_pack(q2.w, q3.w)};

    float bu0 = bu[2 * lane], bu1 = bu[2 * lane + 1];
    float2 tot = make_float2(0.0f, 0.0f);

    int ng = (N + 7) >> 3;
    for (;;) {
        int gpair = next_group2(&g_ticks[1], lane);
        if (gpair >= ng) break;
#pragma unroll 1
        for (int g = gpair; g < gpair + 2 && g < ng; g++) {
            int n0 = g * 8;
            agg_pair(yd, g_Hb, wpa, wpb, n0, 0, half, hl, N);
            agg_pair(yd, g_Hb, wpa, wpb, n0, 1, half, hl, N);
            agg_pair(yd, g_Hb, wpa, wpb, n0, 2, half, hl, N);
            agg_pair(yd, g_Hb, wpa, wpb, n0, 3, half, hl, N);
            __syncwarp();
            ull a2[8] = {0ull, 0ull, 0ull, 0ull, 0ull, 0ull, 0ull, 0ull};
            mv64_8(a2, Wus, yd, lane);
            __syncwarp();
#pragma unroll
            for (int n = 0; n < 8; n++) {
                int nn = n0 + n;
                if (nn < N) {
                    float2 a = d_unpack(a2[n]);
                    tot.x += fmaxf(a.x + bu0, 0.0f);
                    tot.y += fmaxf(a.y + bu1, 0.0f);
                }
            }
        }
    }
    atomicAdd(&sacc[2 * lane], tot.x);
    atomicAdd(&sacc[2 * lane + 1], tot.y);
    __syncthreads();
    if (t < 64) atomicAdd(&out[t], sacc[t] * (1.0f / (float)N));
}

// ---------------- launch ----------------
extern "C" void kernel_launch(void* const* d_in, const int* in_sizes, int n_in,
                              void* d_out, int out_size) {
    const int*   x_ids = (const int*)d_in[0];
    const int*   eidx  = (const int*)d_in[1];
    const float* eattr = (const float*)d_in[2];
    const float* emb   = (const float*)d_in[3];
    const float* W1  = (const float*)d_in[4];
    const float* b1  = (const float*)d_in[5];
    const float* Wu1 = (const float*)d_in[6];
    const float* bu1 = (const float*)d_in[7];
    const float* W2  = (const float*)d_in[8];
    const float* b2  = (const float*)d_in[9];
    const float* Wu2 = (const float*)d_in[10];
    const float* bu2 = (const float*)d_in[11];
    float* out = (float*)d_out;

    int N = in_sizes[0];
    int E = in_sizes[1] / 2;
    int V = in_sizes[3] / D;
    const int* src = eidx;
    const int* dst = eidx + E;

    int nb = (N + 1023) / 1024;
    int gA = nb > V ? nb : V;
    int SB = (E + 255) / 256;
    int GB = (N * 16 + 255) / 256;

    const int R1_SMEM = 65536;   // Wus 16K + Wns 16K + yd 32K
    const int R2_SMEM = 49408;   // Wus 16K + yd 32K + sacc 256B
    cudaFuncSetAttribute(k_round1, cudaFuncAttributeMaxDynamicSharedMemorySize, R1_SMEM);
    cudaFuncSetAttribute(k_round2, cudaFuncAttributeMaxDynamicSharedMemorySize, R2_SMEM);

    k_init<<<gA, 256>>>(emb, W1, b1, out, N, V);
    k_hist_gather<<<SB + GB, 256>>>(dst, x_ids, emb, E, N, SB);
    k_scan<<<nb, 256>>>(N, E, nb);
    k_scatter<<<SB, 256>>>(src, dst, eattr, E);

    const int RG = 444;   // 3 blocks/SM x 148 SMs, single wave
    k_round1<<<RG, 256, R1_SMEM>>>(W1, Wu1, bu1, W2, b2, N);
    k_round2<<<RG, 256, R2_SMEM>>>(W2, Wu2, bu2, out, N);
}

// round 14
// speedup vs baseline: 1.2093x; 1.1170x over previous
#include <cuda_runtime.h>
#include <cuda_fp16.h>

#define D 64
#define MAXN 100000
#define MAXE 1600000
#define MAXV 1024

typedef unsigned long long ull;

// ---------------- f32x2 packed helpers (Blackwell) ----------------
__device__ __forceinline__ ull d_pack(float lo, float hi) {
    ull r; asm("mov.b64 %0, {%1, %2};" : "=l"(r) : "f"(lo), "f"(hi)); return r;
}
__device__ __forceinline__ float2 d_unpack(ull v) {
    float2 r; asm("mov.b64 {%0, %1}, %2;" : "=f"(r.x), "=f"(r.y) : "l"(v)); return r;
}
__device__ __forceinline__ ull d_dup(float v) {
    ull r; asm("mov.b64 %0, {%1, %1};" : "=l"(r) : "f"(v)); return r;
}
__device__ __forceinline__ ull d_fma2(ull a, ull b, ull c) {
    ull d; asm("fma.rn.f32x2 %0, %1, %2, %3;" : "=l"(d) : "l"(a), "l"(b), "l"(c)); return d;
}

// ---------------- static scratch ----------------
__device__ int     g_rowptr[MAXN + 1];
__device__ int     g_cursor[MAXN];
__device__ uint4   g_edge[MAXE];           // {src, ea01(half2), ea23(half2), pad}, dst-sorted
__device__ float   g_X[MAXN * D];          // node features (fp32)
__device__ __half2 g_Ha[MAXN * 32];        // H buffer A (fp16; index i = dims (2i, 2i+1))
__device__ __half2 g_Hb[MAXN * 32];        // H buffer B
__device__ float   g_embH[MAXV * D];       // emb @ Wx1^T + b1
__device__ int     g_aggflag[128];         // per-chunk aggregate | READY bit
__device__ int     g_ticks[2];             // dynamic work counters for round kernels

#define SCAN_READY (1 << 30)

// ---------------- kA: zero cursor/flags/ticks + zero out + embH ----------------
__global__ void k_init(const float* __restrict__ emb, const float* __restrict__ W1,
                       const float* __restrict__ b1, float* __restrict__ out, int N, int V) {
    int b = blockIdx.x, t = threadIdx.x;
    int base = b * 1024 + t * 4;
#pragma unroll
    for (int j = 0; j < 4; j++)
        if (base + j < N) g_cursor[base + j] = 0;
    if (b == 0) {
        if (t < 64) out[t] = 0.0f;
        if (t >= 64 && t < 192) g_aggflag[t - 64] = 0;
        if (t == 192) { g_ticks[0] = 0; g_ticks[1] = 0; }
    }
    if (b < V && t < 64) {
        const float* er = emb + b * D;
        const float* wr = W1 + t * 68;
        float acc = b1[t];
#pragma unroll 16
        for (int j = 0; j < D; j++) acc = fmaf(er[j], wr[j], acc);
        g_embH[b * D + t] = acc;
    }
}

// ---------------- kB: histogram of dst + (parallel) gather X0/Ha ----------------
__global__ void k_hist_gather(const int* __restrict__ dst, const int* __restrict__ ids,
                              const float* __restrict__ emb, int E, int N, int SB) {
    int b = blockIdx.x;
    if (b < SB) {
        int e = b * 256 + threadIdx.x;
        if (e < E) atomicAdd(&g_cursor[dst[e]], 1);
    } else {
        int i = (b - SB) * 256 + threadIdx.x;
        if (i < N * 16) {
            int n = i >> 4, c = i & 15;
            int id = ids[n];
            reinterpret_cast<float4*>(g_X)[i] = reinterpret_cast<const float4*>(emb)[id * 16 + c];
            float4 h4 = reinterpret_cast<const float4*>(g_embH)[id * 16 + c];
            g_Ha[n * 32 + 2 * c]     = __floats2half2_rn(h4.x, h4.y);
            g_Ha[n * 32 + 2 * c + 1] = __floats2half2_rn(h4.z, h4.w);
        }
    }
}

// ---------------- kC: fused scan (local scan + parallel lookback) ----------------
__global__ void k_scan(int N, int E, int nb) {
    __shared__ int s[256];
    int b = blockIdx.x, t = threadIdx.x;
    int base = b * 1024 + t * 4;
    int v0 = (base + 0 < N) ? g_cursor[base + 0] : 0;
    int v1 = (base + 1 < N) ? g_cursor[base + 1] : 0;
    int v2 = (base + 2 < N) ? g_cursor[base + 2] : 0;
    int v3 = (base + 3 < N) ? g_cursor[base + 3] : 0;
    int tsum = v0 + v1 + v2 + v3;
    s[t] = tsum;
    __syncthreads();
    for (int off = 1; off < 256; off <<= 1) {
        int x = (t >= off) ? s[t - off] : 0;
        __syncthreads();
        s[t] += x;
        __syncthreads();
    }
    int excl = s[t] - tsum;
    int total = s[255];
    __syncthreads();
    if (t == 0) atomicExch(&g_aggflag[b], total | SCAN_READY);
    int contrib = 0;
    if (t < b) {
        int v;
        do { v = atomicAdd(&g_aggflag[t], 0); } while (!(v & SCAN_READY));
        contrib = v & (SCAN_READY - 1);
    }
    s[t] = contrib;
    __syncthreads();
    for (int off = 128; off > 0; off >>= 1) {
        if (t < off) s[t] += s[t + off];
        __syncthreads();
    }
    int boff = s[0];
    int r0 = excl + boff;
#pragma unroll
    for (int j = 0; j < 4; j++) {
        int i = base + j;
        if (i < N) {
            g_rowptr[i] = r0;
            g_cursor[i] = r0;
        }
        r0 += (j == 0) ? v0 : (j == 1) ? v1 : v2;
    }
    if (b == 0 && t == 0) g_rowptr[N] = E;
}

// ---------------- kD: scatter packed edge records ----------------
__global__ void k_scatter(const int* __restrict__ src, const int* __restrict__ dst,
                          const float* __restrict__ ea, int E) {
    int e = blockIdx.x * 256 + threadIdx.x;
    if (e < E) {
        int p = atomicAdd(&g_cursor[dst[e]], 1);
        float4 v = *reinterpret_cast<const float4*>(ea + 4 * (size_t)e);
        __half2 e01 = __floats2half2_rn(v.x, v.y);
        __half2 e23 = __floats2half2_rn(v.z, v.w);
        uint4 rec;
        rec.x = (unsigned)src[e];
        rec.y = *reinterpret_cast<const unsigned*>(&e01);
        rec.z = *reinterpret_cast<const unsigned*>(&e23);
        rec.w = 0u;
        g_edge[p] = rec;
    }
}

// ======= shared building blocks for the fused round kernels =======

__device__ __forceinline__ void fill_wint(float* Wf, const float* __restrict__ W, int stride, int t) {
    for (int idx = t; idx < 4096; idx += 256) {
        int jj = idx >> 7, r = idx & 127;
        int l = r >> 2, q = (r >> 1) & 1, h = r & 1;
        Wf[idx] = W[(2 * l + h) * stride + (2 * jj + q)];
    }
}

__device__ __forceinline__ void mv64_8(ull* a2, const ull* Wi, const float* yd8, int lane) {
#pragma unroll 4
    for (int jj = 0; jj < 32; jj++) {
        longlong2 wv = *reinterpret_cast<const longlong2*>(Wi + jj * 64 + 2 * lane);
#pragma unroll
        for (int n = 0; n < 8; n++) {
            longlong2 xv = *reinterpret_cast<const longlong2*>(yd8 + n * 128 + 4 * jj);
            a2[n] = d_fma2((ull)xv.x, (ull)wv.x, a2[n]);
            a2[n] = d_fma2((ull)xv.y, (ull)wv.y, a2[n]);
        }
    }
}

// process one packed edge record for this lane's 4 dims
__device__ __forceinline__ void edge_accum(uint4 rec, uint2 hv,
                                           const ull* wpa, const ull* wpb, bool act,
                                           float& a0, float& a1, float& a2v, float& a3) {
    float2 e01 = __half22float2(*reinterpret_cast<const __half2*>(&rec.y));
    float2 e23 = __half22float2(*reinterpret_cast<const __half2*>(&rec.z));
    float2 h0 = __half22float2(*reinterpret_cast<const __half2*>(&hv.x));
    float2 h1 = __half22float2(*reinterpret_cast<const __half2*>(&hv.y));
    ull m0 = d_pack(h0.x, h0.y);
    ull m1 = d_pack(h1.x, h1.y);
    ull e0 = d_dup(e01.x), e1 = d_dup(e01.y), e2 = d_dup(e23.x), e3 = d_dup(e23.y);
    m0 = d_fma2(e0, wpa[0], m0); m0 = d_fma2(e1, wpa[1], m0);
    m0 = d_fma2(e2, wpa[2], m0); m0 = d_fma2(e3, wpa[3], m0);
    m1 = d_fma2(e0, wpb[0], m1); m1 = d_fma2(e1, wpb[1], m1);
    m1 = d_fma2(e2, wpb[2], m1); m1 = d_fma2(e3, wpb[3], m1);
    if (act) {
        float2 f0 = d_unpack(m0), f1 = d_unpack(m1);
        a0 += fmaxf(f0.x, 0.0f); a1 += fmaxf(f0.y, 0.0f);
        a2v += fmaxf(f1.x, 0.0f); a3 += fmaxf(f1.y, 0.0f);
    }
}

// half-warp agg for node pair (n0+2p, n0+2p+1); lane owns dims 4hl..4hl+3.
// 4-deep software pipeline: batch 4 record LDGs, then 4 H LDGs, then compute (MLP=4).
__device__ __forceinline__ void agg_pair(float* ydrow_base, const __half2* __restrict__ H,
                                         const ull* wpa, const ull* wpb,
                                         int n0, int p, int half, int hl, int N) {
    int nn = n0 + 2 * p + half;
    bool valid = nn < N;
    int nc = valid ? nn : 0;
    int k0 = g_rowptr[nc], k1 = g_rowptr[nc + 1];
    int len = valid ? (k1 - k0) : 0;
    int maxlen = __reduce_max_sync(0xffffffffu, len);
    float a0 = 0.f, a1 = 0.f, a2v = 0.f, a3 = 0.f;
    if (valid) {
        float4 x0 = *reinterpret_cast<const float4*>(g_X + nn * D + 4 * hl);
        a0 = x0.x; a1 = x0.y; a2v = x0.z; a3 = x0.w;
    }
    int i = 0;
    for (; i + 4 <= maxlen; i += 4) {
        bool act0 = (i + 0 < len), act1 = (i + 1 < len);
        bool act2 = (i + 2 < len), act3 = (i + 3 < len);
        uint4 r0 = g_edge[act0 ? (k0 + i + 0) : 0];
        uint4 r1 = g_edge[act1 ? (k0 + i + 1) : 0];
        uint4 r2 = g_edge[act2 ? (k0 + i + 2) : 0];
        uint4 r3 = g_edge[act3 ? (k0 + i + 3) : 0];
        uint2 h0 = *reinterpret_cast<const uint2*>(H + (int)r0.x * 32 + 2 * hl);
        uint2 h1 = *reinterpret_cast<const uint2*>(H + (int)r1.x * 32 + 2 * hl);
        uint2 h2 = *reinterpret_cast<const uint2*>(H + (int)r2.x * 32 + 2 * hl);
        uint2 h3 = *reinterpret_cast<const uint2*>(H + (int)r3.x * 32 + 2 * hl);
        edge_accum(r0, h0, wpa, wpb, act0, a0, a1, a2v, a3);
        edge_accum(r1, h1, wpa, wpb, act1, a0, a1, a2v, a3);
        edge_accum(r2, h2, wpa, wpb, act2, a0, a1, a2v, a3);
        edge_accum(r3, h3, wpa, wpb, act3, a0, a1, a2v, a3);
    }
    if (i < maxlen) {
        bool act0 = (i + 0 < len), act1 = (i + 1 < len), act2 = (i + 2 < len);
        uint4 r0 = g_edge[act0 ? (k0 + i + 0) : 0];
        uint4 r1 = (i + 1 < maxlen) ? g_edge[act1 ? (k0 + i + 1) : 0] : make_uint4(0, 0, 0, 0);
        uint4 r2 = (i + 2 < maxlen) ? g_edge[act2 ? (k0 + i + 2) : 0] : make_uint4(0, 0, 0, 0);
        uint2 h0 = *reinterpret_cast<const uint2*>(H + (int)r0.x * 32 + 2 * hl);
        uint2 h1 = *reinterpret_cast<const uint2*>(H + (int)r1.x * 32 + 2 * hl);
        uint2 h2 = *reinterpret_cast<const uint2*>(H + (int)r2.x * 32 + 2 * hl);
        edge_accum(r0, h0, wpa, wpb, act0, a0, a1, a2v, a3);
        if (i + 1 < maxlen) edge_accum(r1, h1, wpa, wpb, act1, a0, a1, a2v, a3);
        if (i + 2 < maxlen) edge_accum(r2, h2, wpa, wpb, act2, a0, a1, a2v, a3);
    }
    float* row = ydrow_base + (2 * p + half) * 128 + 8 * hl;
    *reinterpret_cast<float4*>(row)     = make_float4(a0, a0, a1, a1);
    *reinterpret_cast<float4*>(row + 4) = make_float4(a2v, a2v, a3, a3);
}

// dynamic ticket: warp-uniform next group index
__device__ __forceinline__ int next_group(int* tick, int lane) {
    int g;
    if (lane == 0) g = atomicAdd(tick, 1);
    return __shfl_sync(0xffffffffu, g, 0);
}

// ---------------- fused round 1 (8 nodes/warp; dynamic smem: Wus|Wns|yd) ----------------
__global__ void __launch_bounds__(256, 3) k_round1(const float* __restrict__ W1,
                                                   const float* __restrict__ Wu, const float* __restrict__ bu,
                                                   const float* __restrict__ Wn, const float* __restrict__ bn,
                                                   int N) {
    extern __shared__ __align__(16) ull smem_dyn[];
    ull* Wus = smem_dyn;                 // 16KB
    ull* Wns = smem_dyn + 2048;          // 16KB
    float* ydall = reinterpret_cast<float*>(smem_dyn + 4096);  // 32KB
    int t = threadIdx.x;
    fill_wint(reinterpret_cast<float*>(Wus), Wu, 64, t);
    fill_wint(reinterpret_cast<float*>(Wns), Wn, 68, t);
    __syncthreads();

    int lane = t & 31, w = t >> 5;
    int half = lane >> 4, hl = lane & 15;
    float* yd = ydall + w * 1024;

    float4 q0 = *reinterpret_cast<const float4*>(W1 + (4 * hl) * 68 + 64);
    float4 q1 = *reinterpret_cast<const float4*>(W1 + (4 * hl + 1) * 68 + 64);
    float4 q2 = *reinterpret_cast<const float4*>(W1 + (4 * hl + 2) * 68 + 64);
    float4 q3 = *reinterpret_cast<const float4*>(W1 + (4 * hl + 3) * 68 + 64);
    ull wpa[4] = {d_pack(q0.x, q1.x), d_pack(q0.y, q1.y), d_pack(q0.z, q1.z), d_pack(q0.w, q1.w)};
    ull wpb[4] = {d_pack(q2.x, q3.x), d_pack(q2.y, q3.y), d_pack(q2.z, q3.z), d_pack(q2.w, q3.w)};

    float bu0 = bu[2 * lane], bu1 = bu[2 * lane + 1];
    float bn0 = bn[2 * lane], bn1 = bn[2 * lane + 1];

    int ng = (N + 7) >> 3;
    for (;;) {
        int g = next_group(&g_ticks[0], lane);
        if (g >= ng) break;
        int n0 = g * 8;
        agg_pair(yd, g_Ha, wpa, wpb, n0, 0, half, hl, N);
        agg_pair(yd, g_Ha, wpa, wpb, n0, 1, half, hl, N);
        agg_pair(yd, g_Ha, wpa, wpb, n0, 2, half, hl, N);
        agg_pair(yd, g_Ha, wpa, wpb, n0, 3, half, hl, N);
        __syncwarp();
        ull a2[8] = {0ull, 0ull, 0ull, 0ull, 0ull, 0ull, 0ull, 0ull};
        mv64_8(a2, Wus, yd, lane);
        __syncwarp();
#pragma unroll
        for (int n = 0; n < 8; n++) {
            float2 a = d_unpack(a2[n]);
            a.x = fmaxf(a.x + bu0, 0.0f);
            a.y = fmaxf(a.y + bu1, 0.0f);
            int nn = n0 + n;
            if (nn < N) *reinterpret_cast<float2*>(g_X + nn * D + 2 * lane) = a;
            *reinterpret_cast<ull*>(&yd[n * 128 + 4 * lane])     = d_dup(a.x);
            *reinterpret_cast<ull*>(&yd[n * 128 + 4 * lane + 2]) = d_dup(a.y);
        }
        __syncwarp();
        ull h2[8] = {0ull, 0ull, 0ull, 0ull, 0ull, 0ull, 0ull, 0ull};
        mv64_8(h2, Wns, yd, lane);
        __syncwarp();
#pragma unroll
        for (int n = 0; n < 8; n++) {
            float2 h = d_unpack(h2[n]);
            int nn = n0 + n;
            if (nn < N) g_Hb[nn * 32 + lane] = __floats2half2_rn(h.x + bn0, h.y + bn1);
        }
    }
}

// ---------------- fused round 2: agg + final matvec + mean ----------------
__global__ void __launch_bounds__(256, 3) k_round2(const float* __restrict__ W2,
                                                   const float* __restrict__ Wu, const float* __restrict__ bu,
                                                   float* __restrict__ out, int N) {
    extern __shared__ __align__(16) ull smem_dyn[];
    ull* Wus = smem_dyn;                                        // 16KB
    float* ydall = reinterpret_cast<float*>(smem_dyn + 2048);   // 32KB
    float* sacc = ydall + 8192;                                 // 64 floats
    int t = threadIdx.x;
    fill_wint(reinterpret_cast<float*>(Wus), Wu, 64, t);
    if (t < 64) sacc[t] = 0.0f;
    __syncthreads();

    int lane = t & 31, w = t >> 5;
    int half = lane >> 4, hl = lane & 15;
    float* yd = ydall + w * 1024;

    float4 q0 = *reinterpret_cast<const float4*>(W2 + (4 * hl) * 68 + 64);
    float4 q1 = *reinterpret_cast<const float4*>(W2 + (4 * hl + 1) * 68 + 64);
    float4 q2 = *reinterpret_cast<const float4*>(W2 + (4 * hl + 2) * 68 + 64);
    float4 q3 = *reinterpret_cast<const float4*>(W2 + (4 * hl + 3) * 68 + 64);
    ull wpa[4] = {d_pack(q0.x, q1.x), d_pack(q0.y, q1.y), d_pack(q0.z, q1.z), d_pack(q0.w, q1.w)};
    ull wpb[4] = {d_pack(q2.x, q3.x), d_pack(q2.y, q3.y), d_pack(q2.z, q3.z), d_pack(q2.w, q3.w)};

    float bu0 = bu[2 * lane], bu1 = bu[2 * lane + 1];
    float2 tot = make_float2(0.0f, 0.0f);

    int ng = (N + 7) >> 3;
    for (;;) {
        int g = next_group(&g_ticks[1], lane);
        if (g >= ng) break;
        int n0 = g * 8;
        agg_pair(yd, g_Hb, wpa, wpb, n0, 0, half, hl, N);
        agg_pair(yd, g_Hb, wpa, wpb, n0, 1, half, hl, N);
        agg_pair(yd, g_Hb, wpa, wpb, n0, 2, half, hl, N);
        agg_pair(yd, g_Hb, wpa, wpb, n0, 3, half, hl, N);
        __syncwarp();
        ull a2[8] = {0ull, 0ull, 0ull, 0ull, 0ull, 0ull, 0ull, 0ull};
        mv64_8(a2, Wus, yd, lane);
        __syncwarp();
#pragma unroll
        for (int n = 0; n < 8; n++) {
            int nn = n0 + n;
            if (nn < N) {
                float2 a = d_unpack(a2[n]);
                tot.x += fmaxf(a.x + bu0, 0.0f);
                tot.y += fmaxf(a.y + bu1, 0.0f);
            }
        }
    }
    atomicAdd(&sacc[2 * lane], tot.x);
    atomicAdd(&sacc[2 * lane + 1], tot.y);
    __syncthreads();
    if (t < 64) atomicAdd(&out[t], sacc[t] * (1.0f / (float)N));
}

// ---------------- launch ----------------
extern "C" void kernel_launch(void* const* d_in, const int* in_sizes, int n_in,
                              void* d_out, int out_size) {
    const int*   x_ids = (const int*)d_in[0];
    const int*   eidx  = (const int*)d_in[1];
    const float* eattr = (const float*)d_in[2];
    const float* emb   = (const float*)d_in[3];
    const float* W1  = (const float*)d_in[4];
    const float* b1  = (const float*)d_in[5];
    const float* Wu1 = (const float*)d_in[6];
    const float* bu1 = (const float*)d_in[7];
    const float* W2  = (const float*)d_in[8];
    const float* b2  = (const float*)d_in[9];
    const float* Wu2 = (const float*)d_in[10];
    const float* bu2 = (const float*)d_in[11];
    float* out = (float*)d_out;

    int N = in_sizes[0];
    int E = in_sizes[1] / 2;
    int V = in_sizes[3] / D;
    const int* src = eidx;
    const int* dst = eidx + E;

    int nb = (N + 1023) / 1024;
    int gA = nb > V ? nb : V;
    int SB = (E + 255) / 256;
    int GB = (N * 16 + 255) / 256;

    const int R1_SMEM = 65536;   // Wus 16K + Wns 16K + yd 32K
    const int R2_SMEM = 49408;   // Wus 16K + yd 32K + sacc 256B
    cudaFuncSetAttribute(k_round1, cudaFuncAttributeMaxDynamicSharedMemorySize, R1_SMEM);
    cudaFuncSetAttribute(k_round2, cudaFuncAttributeMaxDynamicSharedMemorySize, R2_SMEM);

    k_init<<<gA, 256>>>(emb, W1, b1, out, N, V);
    k_hist_gather<<<SB + GB, 256>>>(dst, x_ids, emb, E, N, SB);
    k_scan<<<nb, 256>>>(N, E, nb);
    k_scatter<<<SB, 256>>>(src, dst, eattr, E);

    const int RG = 444;   // 3 blocks/SM x 148 SMs, single wave
    k_round1<<<RG, 256, R1_SMEM>>>(W1, Wu1, bu1, W2, b2, N);
    k_round2<<<RG, 256, R2_SMEM>>>(W2, Wu2, bu2, out, N);
}

// round 15
// speedup vs baseline: 1.2363x; 1.0223x over previous
#include <cuda_runtime.h>
#include <cuda_fp16.h>

#define D 64
#define MAXN 100000
#define MAXE 1600000
#define MAXV 1024

typedef unsigned long long ull;

// ---------------- f32x2 packed helpers (Blackwell) ----------------
__device__ __forceinline__ ull d_pack(float lo, float hi) {
    ull r; asm("mov.b64 %0, {%1, %2};" : "=l"(r) : "f"(lo), "f"(hi)); return r;
}
__device__ __forceinline__ float2 d_unpack(ull v) {
    float2 r; asm("mov.b64 {%0, %1}, %2;" : "=f"(r.x), "=f"(r.y) : "l"(v)); return r;
}
__device__ __forceinline__ ull d_dup(float v) {
    ull r; asm("mov.b64 %0, {%1, %1};" : "=l"(r) : "f"(v)); return r;
}
__device__ __forceinline__ ull d_fma2(ull a, ull b, ull c) {
    ull d; asm("fma.rn.f32x2 %0, %1, %2, %3;" : "=l"(d) : "l"(a), "l"(b), "l"(c)); return d;
}

// ---------------- static scratch ----------------
__device__ int     g_rowptr[MAXN + 1];
__device__ int     g_cursor[MAXN];
__device__ uint4   g_edge[MAXE];           // {src, ea01(half2), ea23(half2), pad}, dst-sorted
__device__ float   g_X[MAXN * D];          // node features (fp32)
__device__ __half2 g_Ha[MAXN * 32];        // H buffer A (fp16; index i = dims (2i, 2i+1))
__device__ __half2 g_Hb[MAXN * 32];        // H buffer B
__device__ float   g_embH[MAXV * D];       // emb @ Wx1^T + b1
__device__ int     g_aggflag[128];         // per-chunk aggregate | READY bit
__device__ int     g_ticks[2];             // dynamic work counters for round kernels

#define SCAN_READY (1 << 30)

// ---------------- kA: zero cursor/flags/ticks + zero out + embH ----------------
__global__ void k_init(const float* __restrict__ emb, const float* __restrict__ W1,
                       const float* __restrict__ b1, float* __restrict__ out, int N, int V) {
    int b = blockIdx.x, t = threadIdx.x;
    int base = b * 1024 + t * 4;
#pragma unroll
    for (int j = 0; j < 4; j++)
        if (base + j < N) g_cursor[base + j] = 0;
    if (b == 0) {
        if (t < 64) out[t] = 0.0f;
        if (t >= 64 && t < 192) g_aggflag[t - 64] = 0;
        if (t == 192) { g_ticks[0] = 0; g_ticks[1] = 0; }
    }
    if (b < V && t < 64) {
        const float* er = emb + b * D;
        const float* wr = W1 + t * 68;
        float acc = b1[t];
#pragma unroll 16
        for (int j = 0; j < D; j++) acc = fmaf(er[j], wr[j], acc);
        g_embH[b * D + t] = acc;
    }
}

// ---------------- kB: histogram of dst + (parallel) gather X0/Ha ----------------
__global__ void k_hist_gather(const int* __restrict__ dst, const int* __restrict__ ids,
                              const float* __restrict__ emb, int E, int N, int SB) {
    int b = blockIdx.x;
    if (b < SB) {
        int e = b * 256 + threadIdx.x;
        if (e < E) atomicAdd(&g_cursor[dst[e]], 1);
    } else {
        int i = (b - SB) * 256 + threadIdx.x;
        if (i < N * 16) {
            int n = i >> 4, c = i & 15;
            int id = ids[n];
            reinterpret_cast<float4*>(g_X)[i] = reinterpret_cast<const float4*>(emb)[id * 16 + c];
            float4 h4 = reinterpret_cast<const float4*>(g_embH)[id * 16 + c];
            g_Ha[n * 32 + 2 * c]     = __floats2half2_rn(h4.x, h4.y);
            g_Ha[n * 32 + 2 * c + 1] = __floats2half2_rn(h4.z, h4.w);
        }
    }
}

// ---------------- kC: fused scan (local scan + parallel lookback) ----------------
__global__ void k_scan(int N, int E, int nb) {
    __shared__ int s[256];
    int b = blockIdx.x, t = threadIdx.x;
    int base = b * 1024 + t * 4;
    int v0 = (base + 0 < N) ? g_cursor[base + 0] : 0;
    int v1 = (base + 1 < N) ? g_cursor[base + 1] : 0;
    int v2 = (base + 2 < N) ? g_cursor[base + 2] : 0;
    int v3 = (base + 3 < N) ? g_cursor[base + 3] : 0;
    int tsum = v0 + v1 + v2 + v3;
    s[t] = tsum;
    __syncthreads();
    for (int off = 1; off < 256; off <<= 1) {
        int x = (t >= off) ? s[t - off] : 0;
        __syncthreads();
        s[t] += x;
        __syncthreads();
    }
    int excl = s[t] - tsum;
    int total = s[255];
    __syncthreads();
    if (t == 0) atomicExch(&g_aggflag[b], total | SCAN_READY);
    int contrib = 0;
    if (t < b) {
        int v;
        do { v = atomicAdd(&g_aggflag[t], 0); } while (!(v & SCAN_READY));
        contrib = v & (SCAN_READY - 1);
    }
    s[t] = contrib;
    __syncthreads();
    for (int off = 128; off > 0; off >>= 1) {
        if (t < off) s[t] += s[t + off];
        __syncthreads();
    }
    int boff = s[0];
    int r0 = excl + boff;
#pragma unroll
    for (int j = 0; j < 4; j++) {
        int i = base + j;
        if (i < N) {
            g_rowptr[i] = r0;
            g_cursor[i] = r0;
        }
        r0 += (j == 0) ? v0 : (j == 1) ? v1 : v2;
    }
    if (b == 0 && t == 0) g_rowptr[N] = E;
}

// ---------------- kD: scatter packed edge records ----------------
__global__ void k_scatter(const int* __restrict__ src, const int* __restrict__ dst,
                          const float* __restrict__ ea, int E) {
    int e = blockIdx.x * 256 + threadIdx.x;
    if (e < E) {
        int p = atomicAdd(&g_cursor[dst[e]], 1);
        float4 v = *reinterpret_cast<const float4*>(ea + 4 * (size_t)e);
        __half2 e01 = __floats2half2_rn(v.x, v.y);
        __half2 e23 = __floats2half2_rn(v.z, v.w);
        uint4 rec;
        rec.x = (unsigned)src[e];
        rec.y = *reinterpret_cast<const unsigned*>(&e01);
        rec.z = *reinterpret_cast<const unsigned*>(&e23);
        rec.w = 0u;
        g_edge[p] = rec;
    }
}

// ======= shared building blocks for the fused round kernels =======

__device__ __forceinline__ void fill_wint(float* Wf, const float* __restrict__ W, int stride, int t) {
    for (int idx = t; idx < 4096; idx += 256) {
        int jj = idx >> 7, r = idx & 127;
        int l = r >> 2, q = (r >> 1) & 1, h = r & 1;
        Wf[idx] = W[(2 * l + h) * stride + (2 * jj + q)];
    }
}

__device__ __forceinline__ void mv64_8(ull* a2, const ull* Wi, const float* yd8, int lane) {
#pragma unroll 4
    for (int jj = 0; jj < 32; jj++) {
        longlong2 wv = *reinterpret_cast<const longlong2*>(Wi + jj * 64 + 2 * lane);
#pragma unroll
        for (int n = 0; n < 8; n++) {
            longlong2 xv = *reinterpret_cast<const longlong2*>(yd8 + n * 128 + 4 * jj);
            a2[n] = d_fma2((ull)xv.x, (ull)wv.x, a2[n]);
            a2[n] = d_fma2((ull)xv.y, (ull)wv.y, a2[n]);
        }
    }
}

// process one packed edge record for this lane's 4 dims
__device__ __forceinline__ void edge_accum(uint4 rec, uint2 hv,
                                           const ull* wpa, const ull* wpb, bool act,
                                           float& a0, float& a1, float& a2v, float& a3) {
    float2 e01 = __half22float2(*reinterpret_cast<const __half2*>(&rec.y));
    float2 e23 = __half22float2(*reinterpret_cast<const __half2*>(&rec.z));
    float2 h0 = __half22float2(*reinterpret_cast<const __half2*>(&hv.x));
    float2 h1 = __half22float2(*reinterpret_cast<const __half2*>(&hv.y));
    ull m0 = d_pack(h0.x, h0.y);
    ull m1 = d_pack(h1.x, h1.y);
    ull e0 = d_dup(e01.x), e1 = d_dup(e01.y), e2 = d_dup(e23.x), e3 = d_dup(e23.y);
    m0 = d_fma2(e0, wpa[0], m0); m0 = d_fma2(e1, wpa[1], m0);
    m0 = d_fma2(e2, wpa[2], m0); m0 = d_fma2(e3, wpa[3], m0);
    m1 = d_fma2(e0, wpb[0], m1); m1 = d_fma2(e1, wpb[1], m1);
    m1 = d_fma2(e2, wpb[2], m1); m1 = d_fma2(e3, wpb[3], m1);
    if (act) {
        float2 f0 = d_unpack(m0), f1 = d_unpack(m1);
        a0 += fmaxf(f0.x, 0.0f); a1 += fmaxf(f0.y, 0.0f);
        a2v += fmaxf(f1.x, 0.0f); a3 += fmaxf(f1.y, 0.0f);
    }
}

// half-warp agg for node pair (n0+2p, n0+2p+1); lane owns dims 4hl..4hl+3.
// Cross-batch software pipeline: batch i+1's records prefetch while batch i's
// H-gathers and compute run (packed uint4 format unchanged — R10-verified).
__device__ __forceinline__ void agg_pair(float* ydrow_base, const __half2* __restrict__ H,
                                         const ull* wpa, const ull* wpb,
                                         int n0, int p, int half, int hl, int N) {
    int nn = n0 + 2 * p + half;
    bool valid = nn < N;
    int nc = valid ? nn : 0;
    int k0 = g_rowptr[nc], k1 = g_rowptr[nc + 1];
    int len = valid ? (k1 - k0) : 0;
    int maxlen = __reduce_max_sync(0xffffffffu, len);
    float a0 = 0.f, a1 = 0.f, a2v = 0.f, a3 = 0.f;
    if (valid) {
        float4 x0 = *reinterpret_cast<const float4*>(g_X + nn * D + 4 * hl);
        a0 = x0.x; a1 = x0.y; a2v = x0.z; a3 = x0.w;
    }
    int i = 0;
    if (maxlen >= 4) {
        // prologue: load batch 0 records
        uint4 r0 = g_edge[(0 < len) ? (k0 + 0) : 0];
        uint4 r1 = g_edge[(1 < len) ? (k0 + 1) : 0];
        uint4 r2 = g_edge[(2 < len) ? (k0 + 2) : 0];
        uint4 r3 = g_edge[(3 < len) ? (k0 + 3) : 0];
        // pipelined main loop: while a FULL next batch exists
        for (; i + 8 <= maxlen; i += 4) {
            uint2 h0 = *reinterpret_cast<const uint2*>(H + (int)r0.x * 32 + 2 * hl);
            uint2 h1 = *reinterpret_cast<const uint2*>(H + (int)r1.x * 32 + 2 * hl);
            uint2 h2 = *reinterpret_cast<const uint2*>(H + (int)r2.x * 32 + 2 * hl);
            uint2 h3 = *reinterpret_cast<const uint2*>(H + (int)r3.x * 32 + 2 * hl);
            uint4 p0 = g_edge[(i + 4 < len) ? (k0 + i + 4) : 0];
            uint4 p1 = g_edge[(i + 5 < len) ? (k0 + i + 5) : 0];
            uint4 p2 = g_edge[(i + 6 < len) ? (k0 + i + 6) : 0];
            uint4 p3 = g_edge[(i + 7 < len) ? (k0 + i + 7) : 0];
            edge_accum(r0, h0, wpa, wpb, i + 0 < len, a0, a1, a2v, a3);
            edge_accum(r1, h1, wpa, wpb, i + 1 < len, a0, a1, a2v, a3);
            edge_accum(r2, h2, wpa, wpb, i + 2 < len, a0, a1, a2v, a3);
            edge_accum(r3, h3, wpa, wpb, i + 3 < len, a0, a1, a2v, a3);
            r0 = p0; r1 = p1; r2 = p2; r3 = p3;
        }
        // epilogue: consume the already-loaded batch (i+4 <= maxlen holds here)
        {
            uint2 h0 = *reinterpret_cast<const uint2*>(H + (int)r0.x * 32 + 2 * hl);
            uint2 h1 = *reinterpret_cast<const uint2*>(H + (int)r1.x * 32 + 2 * hl);
            uint2 h2 = *reinterpret_cast<const uint2*>(H + (int)r2.x * 32 + 2 * hl);
            uint2 h3 = *reinterpret_cast<const uint2*>(H + (int)r3.x * 32 + 2 * hl);
            edge_accum(r0, h0, wpa, wpb, i + 0 < len, a0, a1, a2v, a3);
            edge_accum(r1, h1, wpa, wpb, i + 1 < len, a0, a1, a2v, a3);
            edge_accum(r2, h2, wpa, wpb, i + 2 < len, a0, a1, a2v, a3);
            edge_accum(r3, h3, wpa, wpb, i + 3 < len, a0, a1, a2v, a3);
            i += 4;
        }
    }
    if (i < maxlen) {
        bool act0 = (i + 0 < len), act1 = (i + 1 < len), act2 = (i + 2 < len);
        uint4 r0 = g_edge[act0 ? (k0 + i + 0) : 0];
        uint4 r1 = (i + 1 < maxlen) ? g_edge[act1 ? (k0 + i + 1) : 0] : make_uint4(0, 0, 0, 0);
        uint4 r2 = (i + 2 < maxlen) ? g_edge[act2 ? (k0 + i + 2) : 0] : make_uint4(0, 0, 0, 0);
        uint2 h0 = *reinterpret_cast<const uint2*>(H + (int)r0.x * 32 + 2 * hl);
        uint2 h1 = *reinterpret_cast<const uint2*>(H + (int)r1.x * 32 + 2 * hl);
        uint2 h2 = *reinterpret_cast<const uint2*>(H + (int)r2.x * 32 + 2 * hl);
        edge_accum(r0, h0, wpa, wpb, act0, a0, a1, a2v, a3);
        if (i + 1 < maxlen) edge_accum(r1, h1, wpa, wpb, act1, a0, a1, a2v, a3);
        if (i + 2 < maxlen) edge_accum(r2, h2, wpa, wpb, act2, a0, a1, a2v, a3);
    }
    float* row = ydrow_base + (2 * p + half) * 128 + 8 * hl;
    *reinterpret_cast<float4*>(row)     = make_float4(a0, a0, a1, a1);
    *reinterpret_cast<float4*>(row + 4) = make_float4(a2v, a2v, a3, a3);
}

// dynamic ticket: warp-uniform next group index
__device__ __forceinline__ int next_group(int* tick, int lane) {
    int g;
    if (lane == 0) g = atomicAdd(tick, 1);
    return __shfl_sync(0xffffffffu, g, 0);
}

// ---------------- fused round 1 (8 nodes/warp; dynamic smem: Wus|Wns|yd) ----------------
__global__ void __launch_bounds__(256, 3) k_round1(const float* __restrict__ W1,
                                                   const float* __restrict__ Wu, const float* __restrict__ bu,
                                                   const float* __restrict__ Wn, const float* __restrict__ bn,
                                                   int N) {
    extern __shared__ __align__(16) ull smem_dyn[];
    ull* Wus = smem_dyn;                 // 16KB
    ull* Wns = smem_dyn + 2048;          // 16KB
    float* ydall = reinterpret_cast<float*>(smem_dyn + 4096);  // 32KB
    int t = threadIdx.x;
    fill_wint(reinterpret_cast<float*>(Wus), Wu, 64, t);
    fill_wint(reinterpret_cast<float*>(Wns), Wn, 68, t);
    __syncthreads();

    int lane = t & 31, w = t >> 5;
    int half = lane >> 4, hl = lane & 15;
    float* yd = ydall + w * 1024;

    float4 q0 = *reinterpret_cast<const float4*>(W1 + (4 * hl) * 68 + 64);
    float4 q1 = *reinterpret_cast<const float4*>(W1 + (4 * hl + 1) * 68 + 64);
    float4 q2 = *reinterpret_cast<const float4*>(W1 + (4 * hl + 2) * 68 + 64);
    float4 q3 = *reinterpret_cast<const float4*>(W1 + (4 * hl + 3) * 68 + 64);
    ull wpa[4] = {d_pack(q0.x, q1.x), d_pack(q0.y, q1.y), d_pack(q0.z, q1.z), d_pack(q0.w, q1.w)};
    ull wpb[4] = {d_pack(q2.x, q3.x), d_pack(q2.y, q3.y), d_pack(q2.z, q3.z), d_pack(q2.w, q3.w)};

    float bu0 = bu[2 * lane], bu1 = bu[2 * lane + 1];
    float bn0 = bn[2 * lane], bn1 = bn[2 * lane + 1];

    int ng = (N + 7) >> 3;
    for (;;) {
        int g = next_group(&g_ticks[0], lane);
        if (g >= ng) break;
        int n0 = g * 8;
        agg_pair(yd, g_Ha, wpa, wpb, n0, 0, half, hl, N);
        agg_pair(yd, g_Ha, wpa, wpb, n0, 1, half, hl, N);
        agg_pair(yd, g_Ha, wpa, wpb, n0, 2, half, hl, N);
        agg_pair(yd, g_Ha, wpa, wpb, n0, 3, half, hl, N);
        __syncwarp();
        ull a2[8] = {0ull, 0ull, 0ull, 0ull, 0ull, 0ull, 0ull, 0ull};
        mv64_8(a2, Wus, yd, lane);
        __syncwarp();
#pragma unroll
        for (int n = 0; n < 8; n++) {
            float2 a = d_unpack(a2[n]);
            a.x = fmaxf(a.x + bu0, 0.0f);
            a.y = fmaxf(a.y + bu1, 0.0f);
            int nn = n0 + n;
            if (nn < N) *reinterpret_cast<float2*>(g_X + nn * D + 2 * lane) = a;
            *reinterpret_cast<ull*>(&yd[n * 128 + 4 * lane])     = d_dup(a.x);
            *reinterpret_cast<ull*>(&yd[n * 128 + 4 * lane + 2]) = d_dup(a.y);
        }
        __syncwarp();
        ull h2[8] = {0ull, 0ull, 0ull, 0ull, 0ull, 0ull, 0ull, 0ull};
        mv64_8(h2, Wns, yd, lane);
        __syncwarp();
#pragma unroll
        for (int n = 0; n < 8; n++) {
            float2 h = d_unpack(h2[n]);
            int nn = n0 + n;
            if (nn < N) g_Hb[nn * 32 + lane] = __floats2half2_rn(h.x + bn0, h.y + bn1);
        }
    }
}

// ---------------- fused round 2: agg + final matvec + mean ----------------
__global__ void __launch_bounds__(256, 3) k_round2(const float* __restrict__ W2,
                                                   const float* __restrict__ Wu, const float* __restrict__ bu,
                                                   float* __restrict__ out, int N) {
    extern __shared__ __align__(16) ull smem_dyn[];
    ull* Wus = smem_dyn;                                        // 16KB
    float* ydall = reinterpret_cast<float*>(smem_dyn + 2048);   // 32KB
    float* sacc = ydall + 8192;                                 // 64 floats
    int t = threadIdx.x;
    fill_wint(reinterpret_cast<float*>(Wus), Wu, 64, t);
    if (t < 64) sacc[t] = 0.0f;
    __syncthreads();

    int lane = t & 31, w = t >> 5;
    int half = lane >> 4, hl = lane & 15;
    float* yd = ydall + w * 1024;

    float4 q0 = *reinterpret_cast<const float4*>(W2 + (4 * hl) * 68 + 64);
    float4 q1 = *reinterpret_cast<const float4*>(W2 + (4 * hl + 1) * 68 + 64);
    float4 q2 = *reinterpret_cast<const float4*>(W2 + (4 * hl + 2) * 68 + 64);
    float4 q3 = *reinterpret_cast<const float4*>(W2 + (4 * hl + 3) * 68 + 64);
    ull wpa[4] = {d_pack(q0.x, q1.x), d_pack(q0.y, q1.y), d_pack(q0.z, q1.z), d_pack(q0.w, q1.w)};
    ull wpb[4] = {d_pack(q2.x, q3.x), d_pack(q2.y, q3.y), d_pack(q2.z, q3.z), d_pack(q2.w, q3.w)};

    float bu0 = bu[2 * lane], bu1 = bu[2 * lane + 1];
    float2 tot = make_float2(0.0f, 0.0f);

    int ng = (N + 7) >> 3;
    for (;;) {
        int g = next_group(&g_ticks[1], lane);
        if (g >= ng) break;
        int n0 = g * 8;
        agg_pair(yd, g_Hb, wpa, wpb, n0, 0, half, hl, N);
        agg_pair(yd, g_Hb, wpa, wpb, n0, 1, half, hl, N);
        agg_pair(yd, g_Hb, wpa, wpb, n0, 2, half, hl, N);
        agg_pair(yd, g_Hb, wpa, wpb, n0, 3, half, hl, N);
        __syncwarp();
        ull a2[8] = {0ull, 0ull, 0ull, 0ull, 0ull, 0ull, 0ull, 0ull};
        mv64_8(a2, Wus, yd, lane);
        __syncwarp();
#pragma unroll
        for (int n = 0; n < 8; n++) {
            int nn = n0 + n;
            if (nn < N) {
                float2 a = d_unpack(a2[n]);
                tot.x += fmaxf(a.x + bu0, 0.0f);
                tot.y += fmaxf(a.y + bu1, 0.0f);
            }
        }
    }
    atomicAdd(&sacc[2 * lane], tot.x);
    atomicAdd(&sacc[2 * lane + 1], tot.y);
    __syncthreads();
    if (t < 64) atomicAdd(&out[t], sacc[t] * (1.0f / (float)N));
}

// ---------------- launch ----------------
extern "C" void kernel_launch(void* const* d_in, const int* in_sizes, int n_in,
                              void* d_out, int out_size) {
    const int*   x_ids = (const int*)d_in[0];
    const int*   eidx  = (const int*)d_in[1];
    const float* eattr = (const float*)d_in[2];
    const float* emb   = (const float*)d_in[3];
    const float* W1  = (const float*)d_in[4];
    const float* b1  = (const float*)d_in[5];
    const float* Wu1 = (const float*)d_in[6];
    const float* bu1 = (const float*)d_in[7];
    const float* W2  = (const float*)d_in[8];
    const float* b2  = (const float*)d_in[9];
    const float* Wu2 = (const float*)d_in[10];
    const float* bu2 = (const float*)d_in[11];
    float* out = (float*)d_out;

    int N = in_sizes[0];
    int E = in_sizes[1] / 2;
    int V = in_sizes[3] / D;
    const int* src = eidx;
    const int* dst = eidx + E;

    int nb = (N + 1023) / 1024;
    int gA = nb > V ? nb : V;
    int SB = (E + 255) / 256;
    int GB = (N * 16 + 255) / 256;

    const int R1_SMEM = 65536;   // Wus 16K + Wns 16K + yd 32K
    const int R2_SMEM = 49408;   // Wus 16K + yd 32K + sacc 256B
    cudaFuncSetAttribute(k_round1, cudaFuncAttributeMaxDynamicSharedMemorySize, R1_SMEM);
    cudaFuncSetAttribute(k_round2, cudaFuncAttributeMaxDynamicSharedMemorySize, R2_SMEM);

    k_init<<<gA, 256>>>(emb, W1, b1, out, N, V);
    k_hist_gather<<<SB + GB, 256>>>(dst, x_ids, emb, E, N, SB);
    k_scan<<<nb, 256>>>(N, E, nb);
    k_scatter<<<SB, 256>>>(src, dst, eattr, E);

    const int RG = 444;   // 3 blocks/SM x 148 SMs, single wave
    k_round1<<<RG, 256, R1_SMEM>>>(W1, Wu1, bu1, W2, b2, N);
    k_round2<<<RG, 256, R2_SMEM>>>(W2, Wu2, bu2, out, N);
}